// round 6
// baseline (speedup 1.0000x reference)
#include <cuda_runtime.h>
#include <math.h>

// ---------------- scratch (static device allocations) ----------------
__device__ float g_band[8 * 1024 * 65];   // banded ATA -> L, [b][col][d], fp32
__device__ float g_atb[8 * 1024];         // rhs
__device__ float g_t[2 * 2 * 64 * 1024];  // conv1 outputs [branch][n][c][px]
__device__ float g_att[2 * 24 * 1024];    // sigmoid(conv2 att)
__device__ float g_grad[2 * 24 * 1024];   // conv2 grad
__device__ float g_se[2 * 4];
__device__ float g_sol[8 * 1024];
__device__ float g_ygn[2 * 4 * 1024];

// ---------------- conv1: 64->64 3x3, lrelu, both branches ----------------
__global__ void __launch_bounds__(256) k_conv1(
    const float* __restrict__ x,
    const float* __restrict__ gw1, const float* __restrict__ gb1,
    const float* __restrict__ aw1, const float* __restrict__ ab1)
{
    int plane  = blockIdx.x;           // 0..255
    int branch = plane >> 7;           // 0=grad, 1=att
    int n      = (plane >> 6) & 1;
    int co     = plane & 63;
    const float* wgt  = (branch ? aw1 : gw1) + co * 576;
    float bias        = (branch ? ab1 : gb1)[co];

    __shared__ float xs[34 * 34];
    int row  = threadIdx.x >> 3;        // 0..31
    int col0 = (threadIdx.x & 7) << 2;  // 0..28 step 4

    float a0 = bias, a1 = bias, a2 = bias, a3 = bias;
    const float* xbase = x + n * 64 * 1024;

    for (int ci = 0; ci < 64; ci++) {
        __syncthreads();
        const float* xp = xbase + ci * 1024;
        for (int idx = threadIdx.x; idx < 1156; idx += 256) {
            int r = idx / 34, c = idx - r * 34;
            int gr = r - 1, gc = c - 1;
            xs[idx] = ((unsigned)gr < 32u && (unsigned)gc < 32u) ? xp[gr * 32 + gc] : 0.f;
        }
        __syncthreads();
        float w[9];
#pragma unroll
        for (int k = 0; k < 9; k++) w[k] = __ldg(wgt + ci * 9 + k);
        float s[3][6];
#pragma unroll
        for (int dy = 0; dy < 3; dy++)
#pragma unroll
            for (int dx = 0; dx < 6; dx++)
                s[dy][dx] = xs[(row + dy) * 34 + col0 + dx];
#pragma unroll
        for (int dy = 0; dy < 3; dy++) {
            float w0 = w[dy * 3], w1 = w[dy * 3 + 1], w2 = w[dy * 3 + 2];
            a0 += w0 * s[dy][0] + w1 * s[dy][1] + w2 * s[dy][2];
            a1 += w0 * s[dy][1] + w1 * s[dy][2] + w2 * s[dy][3];
            a2 += w0 * s[dy][2] + w1 * s[dy][3] + w2 * s[dy][4];
            a3 += w0 * s[dy][3] + w1 * s[dy][4] + w2 * s[dy][5];
        }
    }
    float* out = g_t + (((branch * 2 + n) * 64 + co) * 1024) + row * 32 + col0;
    out[0] = a0 > 0.f ? a0 : 0.01f * a0;
    out[1] = a1 > 0.f ? a1 : 0.01f * a1;
    out[2] = a2 > 0.f ? a2 : 0.01f * a2;
    out[3] = a3 > 0.f ? a3 : 0.01f * a3;
}

// ---------------- conv2: 64->24 3x3 (+sigmoid on att branch) ----------------
__global__ void __launch_bounds__(256) k_conv2(
    const float* __restrict__ gw2, const float* __restrict__ gb2,
    const float* __restrict__ aw2, const float* __restrict__ ab2)
{
    int plane  = blockIdx.x;            // 0..95
    int branch = plane / 48;
    int rem    = plane - branch * 48;
    int n      = rem / 24;
    int co     = rem - n * 24;
    const float* wgt = (branch ? aw2 : gw2) + co * 576;
    float bias       = (branch ? ab2 : gb2)[co];

    __shared__ float xs[34 * 34];
    int row  = threadIdx.x >> 3;
    int col0 = (threadIdx.x & 7) << 2;

    float a0 = bias, a1 = bias, a2 = bias, a3 = bias;
    const float* xbase = g_t + (branch * 2 + n) * 64 * 1024;

    for (int ci = 0; ci < 64; ci++) {
        __syncthreads();
        const float* xp = xbase + ci * 1024;
        for (int idx = threadIdx.x; idx < 1156; idx += 256) {
            int r = idx / 34, c = idx - r * 34;
            int gr = r - 1, gc = c - 1;
            xs[idx] = ((unsigned)gr < 32u && (unsigned)gc < 32u) ? xp[gr * 32 + gc] : 0.f;
        }
        __syncthreads();
        float w[9];
#pragma unroll
        for (int k = 0; k < 9; k++) w[k] = __ldg(wgt + ci * 9 + k);
        float s[3][6];
#pragma unroll
        for (int dy = 0; dy < 3; dy++)
#pragma unroll
            for (int dx = 0; dx < 6; dx++)
                s[dy][dx] = xs[(row + dy) * 34 + col0 + dx];
#pragma unroll
        for (int dy = 0; dy < 3; dy++) {
            float w0 = w[dy * 3], w1 = w[dy * 3 + 1], w2 = w[dy * 3 + 2];
            a0 += w0 * s[dy][0] + w1 * s[dy][1] + w2 * s[dy][2];
            a1 += w0 * s[dy][1] + w1 * s[dy][2] + w2 * s[dy][3];
            a2 += w0 * s[dy][2] + w1 * s[dy][3] + w2 * s[dy][4];
            a3 += w0 * s[dy][3] + w1 * s[dy][4] + w2 * s[dy][5];
        }
    }
    float* out = (branch ? g_att : g_grad) + ((n * 24 + co) * 1024) + row * 32 + col0;
    if (branch) {
        out[0] = 1.f / (1.f + expf(-a0));
        out[1] = 1.f / (1.f + expf(-a1));
        out[2] = 1.f / (1.f + expf(-a2));
        out[3] = 1.f / (1.f + expf(-a3));
    } else {
        out[0] = a0; out[1] = a1; out[2] = a2; out[3] = a3;
    }
}

// ---------------- SE branch ----------------
__global__ void __launch_bounds__(256) k_se(
    const float* __restrict__ x,
    const float* __restrict__ sw1, const float* __restrict__ sb1,
    const float* __restrict__ sw2, const float* __restrict__ sb2)
{
    int n = blockIdx.x, tid = threadIdx.x;
    __shared__ float red[256];
    __shared__ float pooled[64];
    __shared__ float s1[32];

    int c = tid >> 2, part = tid & 3;
    const float* xp = x + (n * 64 + c) * 1024 + part * 256;
    float s = 0.f;
    for (int i = 0; i < 256; i++) s += xp[i];
    red[tid] = s;
    __syncthreads();
    if (part == 0)
        pooled[c] = (red[tid] + red[tid + 1] + red[tid + 2] + red[tid + 3]) * (1.f / 1024.f);
    __syncthreads();
    if (tid < 32) {
        float a = sb1[tid];
        for (int j = 0; j < 64; j++) a += sw1[tid * 64 + j] * pooled[j];
        s1[tid] = a > 0.f ? a : 0.01f * a;
    }
    __syncthreads();
    if (tid < 4) {
        float a = sb2[tid];
        for (int j = 0; j < 32; j++) a += sw2[tid * 32 + j] * s1[j];
        g_se[n * 4 + tid] = 1.f / (1.f + expf(-a));
    }
}

// ---------------- build banded ATA + ATB: deterministic gather ----------------
__global__ void __launch_bounds__(256) k_build(const float* __restrict__ a)
{
    int t = blockIdx.x * blockDim.x + threadIdx.x;   // 0..8191
    int b = t >> 10;
    int q = t & 1023;
    int n = b >> 2;
    int g = b & 3;
    const int offs[7] = {0, 1, 2, 31, 32, 33, 64};

    float acc[11];
    const int DVALS[11] = {0, 1, 2, 29, 30, 31, 32, 33, 62, 63, 64};
#pragma unroll
    for (int z = 0; z < 11; z++) acc[z] = 0.f;
    acc[0] = 1e-12f;
    float atb = 0.f;

#pragma unroll
    for (int k = 0; k < 6; k++) {
        int ch = g * 6 + k;
        const float* attp  = g_att  + (n * 24 + ch) * 1024;
        const float* gradp = g_grad + (n * 24 + ch) * 1024;
#pragma unroll
        for (int c2 = 0; c2 < 7; c2++) {
            int i = q - offs[c2];
            if (i >= 0) {
                float attv = attp[i];
                float at2  = attv * attv;
                const float* arow = a + (size_t)(i * 6 + k) * 1024;
                float v2 = arow[q];
                if (v2 != 0.f) {
                    atb += v2 * at2 * gradp[i];
                    float w2 = v2 * at2;
#pragma unroll
                    for (int c1 = c2; c1 < 7; c1++) {
                        int col1 = i + offs[c1];
                        if (col1 <= 1023) {
                            float contrib = arow[col1] * w2;
                            int d = offs[c1] - offs[c2];
#pragma unroll
                            for (int z = 0; z < 11; z++)
                                if (DVALS[z] == d) acc[z] += contrib;
                        }
                    }
                }
            }
        }
    }

    float* bc = g_band + ((size_t)b * 1024 + q) * 65;
#pragma unroll
    for (int d = 0; d < 65; d++) {
        float v = 0.f;
#pragma unroll
        for (int z = 0; z < 11; z++)
            if (DVALS[z] == d) v = acc[z];
        bc[d] = v;
    }
    g_atb[b * 1024 + q] = atb;
}

// ---------------- banded Cholesky, fp32, chunked float4 rank-1 updates -------
// W ring window: 65 columns (slot = col % 65), stride 68 floats (keeps 16B
// alignment of 8-aligned d offsets under the +68/step ring advance).
// Pairs (p,q), 1<=p<=q<=64, q-p=d: rows p=1..63 are split into 287 chunks of
// 8 consecutive d (rows padded to x8; padded q>64 reads Lsm pad = 0 -> exact
// no-op update of a real cell). Pair (64,64) stays fused into the committer.
// Per step: phase LOADS (2x LDS.128 on W + 8 scalar lq + lp), COMPUTE, STORES
// (2x STS.128). Row-1 chunk owners (tid 0..7) publish column j+1 to the
// alternate Lsm buffer; tid 0 computes next pivot rsqrt; tid 190 copies the
// d=64 entry; tids 191..255 do diag/L-writeout/forward-sub/commit/prefetch.
// One __syncthreads per column step.
__global__ void __launch_bounds__(256) k_solve()
{
    const int WS = 68;                 // W column stride
    const int WN = 65 * WS;            // 4420
    int b   = blockIdx.x;
    int tid = threadIdx.x;
    float* band = g_band + (size_t)b * 1024 * 65;

    __shared__ __align__(16) float W[65 * 68];
    __shared__ __align__(16) float Lsm[2 * 72];   // pad d=65..71 = 0
    __shared__ float y_s[1100];
    __shared__ float x_s[1024];
    __shared__ float s_inv[2];

    // ---- decode chunk(s): (p, A = slot(p)*WS + d0, qb = p + d0) ----
#define DECODE_CHUNK(IDX, P, A, QB) {                                   \
        int _c = (IDX); int _p = 1;                                     \
        for (;;) { int _nb = (72 - _p) >> 3;                            \
                   if (_c < _nb) break; _c -= _nb; _p++; }              \
        int _d0 = _c << 3;                                              \
        P = _p; A = _p * WS + _d0; QB = _p + _d0; }
    int p1c, A1, qb1;
    DECODE_CHUNK(tid, p1c, A1, qb1)
    bool has2 = (tid < 31);
    int p2c = 1, A2 = WS, qb2 = 1;
    if (has2) DECODE_CHUNK(256 + tid, p2c, A2, qb2)
#undef DECODE_CHUNK

    // ---- committer role registers (tid 191..255 -> r = 0..64) ----
    int r  = tid - 191;
    int lw = r;                        // gmem L write index (stride 65)
    int cm = 64 * WS + r;              // W commit addr (col 64 slot)
    int pf = 68 * 65 + r;              // gmem prefetch index (col 68)
    float P0 = 0.f, P1v = 0.f, P2v = 0.f, P3v = 0.f;
    int a65 = 1 * WS + 64;             // tid 190: W addr of (col j+1, d=64)

    // ---- init ----
    for (int j = tid; j < 1024; j += 256) y_s[j] = g_atb[b * 1024 + j];
    for (int j = 1024 + tid; j < 1100; j += 256) y_s[j] = 0.f;
    for (int idx = tid; idx < 64 * 65; idx += 256) {
        int c = idx / 65, d = idx - c * 65;
        W[c * WS + d] = band[idx];
    }
    if (tid >= 191) {
        P0  = band[64 * 65 + r];
        P1v = band[65 * 65 + r];
        P2v = band[66 * 65 + r];
        P3v = band[67 * 65 + r];
    }
    if (tid < 7) { Lsm[65 + tid] = 0.f; Lsm[72 + 65 + tid] = 0.f; }
    __syncthreads();
    if (tid >= 191) {
        Lsm[r] = W[r];                 // publish column 0 (slot 0)
        if (r == 0) {
            float d0 = W[0];
            float rr = rsqrtf(d0);
            s_inv[0] = rr * (1.5f - 0.5f * d0 * rr * rr);
        }
    }
    __syncthreads();

    // ---- main factorization loop: 1 barrier per column ----
    for (int j = 0; j < 1024; j++) {
        int bb = j & 1;
        int nb = bb ^ 1;
        const float* Lb = Lsm + bb * 72;
        float inv  = s_inv[bb];
        float inv2 = inv * inv;
        bool have_in = (j < 960);

        // ======== LOAD PHASE (no stores yet -> ptxas batches the LDS) ======
        float lp1 = Lb[p1c];
        float4 w1a = *(const float4*)&W[A1];
        float4 w1b = *(const float4*)&W[A1 + 4];
        float q10 = Lb[qb1 + 0], q11 = Lb[qb1 + 1], q12 = Lb[qb1 + 2], q13 = Lb[qb1 + 3];
        float q14 = Lb[qb1 + 4], q15 = Lb[qb1 + 5], q16 = Lb[qb1 + 6], q17 = Lb[qb1 + 7];

        float lp2 = 0.f;
        float4 w2a = make_float4(0.f, 0.f, 0.f, 0.f), w2b = w2a;
        float q20 = 0.f, q21 = 0.f, q22 = 0.f, q23 = 0.f;
        float q24 = 0.f, q25 = 0.f, q26 = 0.f, q27 = 0.f;
        if (has2) {
            lp2 = Lb[p2c];
            w2a = *(const float4*)&W[A2];
            w2b = *(const float4*)&W[A2 + 4];
            q20 = Lb[qb2 + 0]; q21 = Lb[qb2 + 1]; q22 = Lb[qb2 + 2]; q23 = Lb[qb2 + 3];
            q24 = Lb[qb2 + 4]; q25 = Lb[qb2 + 5]; q26 = Lb[qb2 + 6]; q27 = Lb[qb2 + 7];
        }
        float wv = 0.f, yj = 0.f, l64 = 0.f;
        if (tid >= 191) { wv = Lb[r]; yj = y_s[j]; l64 = Lb[64]; }
        float w64v = 0.f;
        if (tid == 190) w64v = W[a65];

        // ======== COMPUTE + STORE chunk 1 ========
        float f1 = lp1 * inv2;
        float4 n1a, n1b;
        n1a.x = w1a.x - q10 * f1;  n1a.y = w1a.y - q11 * f1;
        n1a.z = w1a.z - q12 * f1;  n1a.w = w1a.w - q13 * f1;
        n1b.x = w1b.x - q14 * f1;  n1b.y = w1b.y - q15 * f1;
        n1b.z = w1b.z - q16 * f1;  n1b.w = w1b.w - q17 * f1;
        *(float4*)&W[A1] = n1a;
        *(float4*)&W[A1 + 4] = n1b;
        if (tid < 8) {                 // row p=1: publish column j+1
            int pb_ = nb * 72 + (qb1 - 1);   // d0 = qb1 - 1, multiple of 8
            *(float4*)&Lsm[pb_]     = n1a;
            *(float4*)&Lsm[pb_ + 4] = n1b;
            if (tid == 0) {
                float nv = n1a.x;
                float rr = rsqrtf(nv);
                s_inv[nb] = rr * (1.5f - 0.5f * nv * rr * rr);
            }
        }
        A1 += WS; if (A1 >= WN) A1 -= WN;

        // ======== COMPUTE + STORE chunk 2 ========
        if (has2) {
            float f2 = lp2 * inv2;
            float4 n2a, n2b;
            n2a.x = w2a.x - q20 * f2;  n2a.y = w2a.y - q21 * f2;
            n2a.z = w2a.z - q22 * f2;  n2a.w = w2a.w - q23 * f2;
            n2b.x = w2b.x - q24 * f2;  n2b.y = w2b.y - q25 * f2;
            n2b.z = w2b.z - q26 * f2;  n2b.w = w2b.w - q27 * f2;
            *(float4*)&W[A2] = n2a;
            *(float4*)&W[A2 + 4] = n2b;
            A2 += WS; if (A2 >= WN) A2 -= WN;
        }

        // ======== publish d=64 of col j+1 ========
        if (tid == 190) {
            Lsm[nb * 72 + 64] = w64v;
            a65 += WS; if (a65 >= WN) a65 -= WN;
        }

        // ======== committer: diag / L write / fwd-sub / commit / prefetch ==
        if (tid >= 191) {
            if (r == 0) {
                band[lw] = inv;                  // store INVERSE diag
                x_s[j] = yj * inv;
                if (have_in) W[cm] = P0 - l64 * l64 * inv2;  // + pair (64,64)
            } else {
                float Lr = wv * inv;
                band[lw] = Lr;
                y_s[j + r] -= Lr * (yj * inv);
                if (have_in) W[cm] = P0;
            }
            P0 = P1v; P1v = P2v; P2v = P3v;
            P3v = (pf < 66560) ? band[pf] : 0.f;
            pf += 65;
            cm += WS; if (cm >= WN) cm -= WN;
            lw += 65;
        }
        __syncthreads();
    }

    // ---- back substitution: L^T x = y', blocked by 64 rows (reuse W) ----
    float* LB = W;   // stride-65 layout here
    for (int blk = 15; blk >= 0; blk--) {
        int j0 = blk * 64;
        for (int idx = tid; idx < 64 * 65; idx += 256)
            LB[idx] = band[j0 * 65 + idx];
        __syncthreads();
        if (tid < 64) {
            int t = tid, jj = j0 + t;
            float s = 0.f;
            for (int rr = 64 - t; rr <= 64; rr++) {
                int jr = jj + rr;
                if (jr < 1024) s += LB[t * 65 + rr] * x_s[jr];
            }
            x_s[jj] -= s;
        }
        __syncthreads();
        for (int t = 63; t >= 1; t--) {
            float xval = x_s[j0 + t] * LB[t * 65];
            if (tid < t) x_s[j0 + tid] -= LB[tid * 65 + (t - tid)] * xval;
            __syncthreads();
        }
        if (tid < 64) x_s[j0 + tid] *= LB[tid * 65];
        __syncthreads();
    }

    for (int j = tid; j < 1024; j += 256) g_sol[b * 1024 + j] = x_s[j];
}

// ---------------- GroupNorm(1, GR) + affine + SE scale ----------------
__global__ void __launch_bounds__(256) k_gn(const float* __restrict__ gn_g,
                                            const float* __restrict__ gn_b)
{
    int n = blockIdx.x, tid = threadIdx.x;
    __shared__ double s1[256], s2[256];
    double a = 0.0, c = 0.0;
    for (int idx = tid; idx < 4096; idx += 256) {
        double v = g_sol[n * 4096 + idx];
        a += v; c += v * v;
    }
    s1[tid] = a; s2[tid] = c;
    __syncthreads();
    for (int off = 128; off > 0; off >>= 1) {
        if (tid < off) { s1[tid] += s1[tid + off]; s2[tid] += s2[tid + off]; }
        __syncthreads();
    }
    double mu  = s1[0] * (1.0 / 4096.0);
    double var = s2[0] * (1.0 / 4096.0) - mu * mu;
    double invstd = rsqrt(var + 1e-5);
    for (int idx = tid; idx < 4096; idx += 256) {
        int g = idx >> 10;
        float v = (float)((g_sol[n * 4096 + idx] - mu) * invstd);
        v = v * gn_g[g] + gn_b[g];
        v *= g_se[n * 4 + g];
        g_ygn[n * 4096 + idx] = v;
    }
}

// ---------------- final conv: 4->128 3x3 ----------------
__global__ void __launch_bounds__(256) k_convf(
    const float* __restrict__ pw, const float* __restrict__ pb,
    float* __restrict__ out)
{
    int plane = blockIdx.x;          // 0..255
    int n  = plane >> 7;
    int co = plane & 127;
    __shared__ float ys[4 * 1156];
    for (int idx = threadIdx.x; idx < 4 * 1156; idx += 256) {
        int ci = idx / 1156, rr = idx - ci * 1156;
        int r = rr / 34, c = rr - r * 34;
        int gr = r - 1, gc = c - 1;
        ys[idx] = ((unsigned)gr < 32u && (unsigned)gc < 32u)
                  ? g_ygn[(n * 4 + ci) * 1024 + gr * 32 + gc] : 0.f;
    }
    __syncthreads();

    const float* wgt = pw + co * 36;
    float bias = pb[co];
    int row  = threadIdx.x >> 3;
    int col0 = (threadIdx.x & 7) << 2;
    float a0 = bias, a1 = bias, a2 = bias, a3 = bias;
#pragma unroll
    for (int ci = 0; ci < 4; ci++) {
        float w[9];
#pragma unroll
        for (int k = 0; k < 9; k++) w[k] = __ldg(wgt + ci * 9 + k);
        float s[3][6];
#pragma unroll
        for (int dy = 0; dy < 3; dy++)
#pragma unroll
            for (int dx = 0; dx < 6; dx++)
                s[dy][dx] = ys[ci * 1156 + (row + dy) * 34 + col0 + dx];
#pragma unroll
        for (int dy = 0; dy < 3; dy++) {
            float w0 = w[dy * 3], w1 = w[dy * 3 + 1], w2 = w[dy * 3 + 2];
            a0 += w0 * s[dy][0] + w1 * s[dy][1] + w2 * s[dy][2];
            a1 += w0 * s[dy][1] + w1 * s[dy][2] + w2 * s[dy][3];
            a2 += w0 * s[dy][2] + w1 * s[dy][3] + w2 * s[dy][4];
            a3 += w0 * s[dy][3] + w1 * s[dy][4] + w2 * s[dy][5];
        }
    }
    float* o = out + ((n * 128 + co) * 1024) + row * 32 + col0;
    o[0] = a0; o[1] = a1; o[2] = a2; o[3] = a3;
}

// ---------------- launcher ----------------
extern "C" void kernel_launch(void* const* d_in, const int* in_sizes, int n_in,
                              void* d_out, int out_size)
{
    const float* x    = (const float*)d_in[0];
    const float* a    = (const float*)d_in[1];
    const float* gw1  = (const float*)d_in[2];
    const float* gb1  = (const float*)d_in[3];
    const float* gw2  = (const float*)d_in[4];
    const float* gb2  = (const float*)d_in[5];
    const float* aw1  = (const float*)d_in[6];
    const float* ab1  = (const float*)d_in[7];
    const float* aw2  = (const float*)d_in[8];
    const float* ab2  = (const float*)d_in[9];
    const float* sw1  = (const float*)d_in[10];
    const float* sb1  = (const float*)d_in[11];
    const float* sw2  = (const float*)d_in[12];
    const float* sb2  = (const float*)d_in[13];
    const float* gn_g = (const float*)d_in[14];
    const float* gn_b = (const float*)d_in[15];
    const float* pw   = (const float*)d_in[16];
    const float* pb   = (const float*)d_in[17];
    float* out = (float*)d_out;

    k_conv1<<<256, 256>>>(x, gw1, gb1, aw1, ab1);
    k_conv2<<<96, 256>>>(gw2, gb2, aw2, ab2);
    k_se<<<2, 256>>>(x, sw1, sb1, sw2, sb2);
    k_build<<<32, 256>>>(a);
    k_solve<<<8, 256>>>();
    k_gn<<<2, 256>>>(gn_g, gn_b);
    k_convf<<<256, 256>>>(pw, pb, out);
}